// round 6
// baseline (speedup 1.0000x reference)
#include <cuda_runtime.h>
#include <math.h>

#define BATCH 16
#define TQ 4
#define DMODEL 2048
#define NH 8
#define NG 4
#define GSZ 2
#define HD 256
#define KVBLK 16
#define WINDOW 1024
#define NBLK 257
#define NTOK 64          // BATCH*TQ
#define NFQKV 4096       // 2048 q + 1024 k + 1024 v
#define NSPLIT 6         // attention KV splits (384 CTAs = one wave)
#define NPART (NSPLIT*2) // partials per query (splits x key-halves)
#define QKV_SPL 4        // split-K for QKV GEMM (128 CTAs)
#define O_SPL 8          // split-K for O GEMM (128 CTAs)

// ---------------- scratch (device globals; no allocation allowed) ----------
__device__ float g_part_qkv[QKV_SPL][NTOK][NFQKV];      // 4 MB
__device__ float g_xT[DMODEL][NTOK];                    // tf32-rounded x^T
__device__ float g_oT[DMODEL][NTOK];                    // tf32-rounded attn-out^T
__device__ float g_q[NTOK][NH][HD];
__device__ float g_k[NTOK][NG][HD];
__device__ float g_v[NTOK][NG][HD];
__device__ float g_cos[NTOK][HD / 2];
__device__ float g_sin[NTOK][HD / 2];
__device__ float g_pacc[BATCH * NG * 8 * NPART][HD];    // 6 MB
__device__ float g_pm[BATCH * NG * 8 * NPART];
__device__ float g_pl[BATCH * NG * 8 * NPART];
__device__ float g_part_out[O_SPL][NTOK][DMODEL];       // 4 MB

// ---------------- cp.async / mma helpers ------------------------------------
__device__ __forceinline__ void cp_async16(void* dst, const void* src)
{
    unsigned d = (unsigned)__cvta_generic_to_shared(dst);
    asm volatile("cp.async.cg.shared.global [%0], [%1], 16;\n" :: "r"(d), "l"(src));
}
__device__ __forceinline__ void cp_commit()
{
    asm volatile("cp.async.commit_group;\n");
}
template <int N>
__device__ __forceinline__ void cp_wait()
{
    asm volatile("cp.async.wait_group %0;\n" :: "n"(N));
}
__device__ __forceinline__ unsigned f2tf32(float f)
{
    unsigned u;
    asm("cvt.rna.tf32.f32 %0, %1;" : "=r"(u) : "f"(f));
    return u;
}
__device__ __forceinline__ void mma_tf32(float* d, const unsigned* a, const unsigned* b)
{
    asm volatile(
        "mma.sync.aligned.m16n8k8.row.col.f32.tf32.tf32.f32 "
        "{%0,%1,%2,%3}, {%4,%5,%6,%7}, {%8,%9}, {%0,%1,%2,%3};\n"
        : "+f"(d[0]), "+f"(d[1]), "+f"(d[2]), "+f"(d[3])
        : "r"(a[0]), "r"(a[1]), "r"(a[2]), "r"(a[3]), "r"(b[0]), "r"(b[1]));
}

// ---------------- x -> g_xT transpose + tf32 round --------------------------
__global__ void k_transpose_x(const float* __restrict__ x)
{
    __shared__ float tile[32][33];
    const int kb = blockIdx.x * 32;     // k base
    const int tb = blockIdx.y * 32;     // token base
    const int tx = threadIdx.x, ty = threadIdx.y;   // (32, 8)
#pragma unroll
    for (int i = 0; i < 32; i += 8)
        tile[ty + i][tx] = x[(size_t)(tb + ty + i) * DMODEL + kb + tx];
    __syncthreads();
#pragma unroll
    for (int i = 0; i < 32; i += 8) {
        float v = tile[tx][ty + i];
        g_xT[kb + ty + i][tb + tx] = __uint_as_float(f2tf32(v));
    }
}

// ---------------- tf32 tensor-core split-K GEMM -----------------------------
// C[64, NF] = A[64, 2048] * W[NF, 2048]^T, A pre-transposed/rounded in AT.
// CTA tile: 64 tokens x 128 features; K chunk 32 (NCHUNK chunks, double-buf).
// 8 warps = 2(M) x 4(N); warp tile 32x32 = 2x4 m16n8k8 mma tiles.
template <int NF, int NCHUNK>
__device__ __forceinline__ void gemm_tc(
    const float* __restrict__ AT,
    const float* __restrict__ W0, int n0,
    const float* __restrict__ W1, int n1,
    const float* __restrict__ W2,
    float* __restrict__ part)
{
    __shared__ float As[2][32][72];    // [k][m], stride 72 -> conflict-free frags
    __shared__ float Ws[2][128][36];   // [n][k], stride 36 -> conflict-free frags

    const int fbase = blockIdx.x * 128;
    const int split = blockIdx.y;
    const int tid = threadIdx.x;
    const int lane = tid & 31, warp = tid >> 5;
    const int wm = warp >> 2, wn = warp & 3;
    const int kbase = split * (NCHUNK * 32);
    const int gid = lane >> 2, tig = lane & 3;

    float acc[2][4][4] = {};

    auto issue = [&](int c, int buf) {
        const int kg = kbase + c * 32;
#pragma unroll
        for (int r = 0; r < 2; r++) {
            int o = tid * 2 + r;                    // 0..511
            int row = o >> 4, seg = o & 15;
            cp_async16(&As[buf][row][seg * 4],
                       &AT[(size_t)(kg + row) * NTOK + seg * 4]);
        }
#pragma unroll
        for (int r = 0; r < 4; r++) {
            int o = tid * 4 + r;                    // 0..1023
            int n = o >> 3, seg = o & 7;
            int f = fbase + n;
            const float* wr;
            if (f < n0)            wr = W0 + (size_t)f * DMODEL;
            else if (f < n0 + n1)  wr = W1 + (size_t)(f - n0) * DMODEL;
            else                   wr = W2 + (size_t)(f - n0 - n1) * DMODEL;
            cp_async16(&Ws[buf][n][seg * 4], wr + kg + seg * 4);
        }
        cp_commit();
    };

    issue(0, 0);
    int buf = 0;
    for (int c = 0; c < NCHUNK; c++) {
        if (c < NCHUNK - 1) { issue(c + 1, buf ^ 1); cp_wait<1>(); }
        else                cp_wait<0>();
        __syncthreads();
#pragma unroll
        for (int ks = 0; ks < 4; ks++) {
            const int k = ks * 8 + tig;
            unsigned aF[2][4], bF[4][2];
#pragma unroll
            for (int mt = 0; mt < 2; mt++) {
                int m = wm * 32 + mt * 16 + gid;
                aF[mt][0] = __float_as_uint(As[buf][k][m]);        // pre-rounded
                aF[mt][1] = __float_as_uint(As[buf][k][m + 8]);
                aF[mt][2] = __float_as_uint(As[buf][k + 4][m]);
                aF[mt][3] = __float_as_uint(As[buf][k + 4][m + 8]);
            }
#pragma unroll
            for (int nt = 0; nt < 4; nt++) {
                int n = wn * 32 + nt * 8 + gid;
                bF[nt][0] = f2tf32(Ws[buf][n][k]);
                bF[nt][1] = f2tf32(Ws[buf][n][k + 4]);
            }
#pragma unroll
            for (int mt = 0; mt < 2; mt++)
#pragma unroll
                for (int nt = 0; nt < 4; nt++)
                    mma_tf32(acc[mt][nt], aF[mt], bF[nt]);
        }
        buf ^= 1;
        __syncthreads();
    }

#pragma unroll
    for (int mt = 0; mt < 2; mt++)
#pragma unroll
        for (int nt = 0; nt < 4; nt++) {
            int m = wm * 32 + mt * 16 + gid;
            int f = fbase + wn * 32 + nt * 8 + tig * 2;
            *(float2*)&part[((size_t)split * NTOK + m) * NF + f] =
                make_float2(acc[mt][nt][0], acc[mt][nt][1]);
            *(float2*)&part[((size_t)split * NTOK + m + 8) * NF + f] =
                make_float2(acc[mt][nt][2], acc[mt][nt][3]);
        }
}

__global__ void __launch_bounds__(256)
k_gemm_qkv(const float* __restrict__ Wq,
           const float* __restrict__ Wk,
           const float* __restrict__ Wv)
{
    gemm_tc<NFQKV, DMODEL / QKV_SPL / 32>(
        &g_xT[0][0], Wq, 2048, Wk, 1024, Wv, &g_part_qkv[0][0][0]);
}

__global__ void __launch_bounds__(256)
k_gemm_o(const float* __restrict__ Wo)
{
    gemm_tc<DMODEL, DMODEL / O_SPL / 32>(
        &g_oT[0][0], Wo, 2048, Wo, 0, Wo, &g_part_out[0][0][0]);
}

// ---------------- RoPE table (fp64 accuracy) --------------------------------
__global__ void k_rope_table(const int* __restrict__ kv_lens)
{
    int idx = blockIdx.x * blockDim.x + threadIdx.x;   // 64*128
    if (idx >= NTOK * 128) return;
    int bt = idx >> 7, j = idx & 127;
    int b = bt >> 2, t = bt & 3;
    int pos = kv_lens[b] + t;
    double inv = exp(-((double)j / 128.0) * log(10000.0));
    double ang = (double)pos * inv;
    double sd, cd;
    sincos(ang, &sd, &cd);
    g_cos[bt][j] = (float)cd;
    g_sin[bt][j] = (float)sd;
}

// ---------------- split-K reduce + RMSNorm + RoPE + store q/k/v ------------
__global__ void k_normrope(const float* __restrict__ q_scale,
                           const float* __restrict__ k_scale)
{
    const int bt = blockIdx.x;
    const int u = blockIdx.y;
    const int d = threadIdx.x;      // 0..255

    int f;
    if (u < 8)       f = u * HD + d;
    else if (u < 12) f = 2048 + (u - 8) * HD + d;
    else             f = 3072 + (u - 12) * HD + d;

    float v = 0.f;
#pragma unroll
    for (int s = 0; s < QKV_SPL; s++) v += g_part_qkv[s][bt][f];

    if (u >= 12) { g_v[bt][u - 12][d] = v; return; }

    __shared__ float red[256];
    __shared__ float sx[256];
    red[d] = v * v;
    __syncthreads();
    for (int s = 128; s > 0; s >>= 1) {
        if (d < s) red[d] += red[d + s];
        __syncthreads();
    }
    float rn = rsqrtf(red[0] / (float)HD + 1e-6f);
    float sc = (u < 8) ? q_scale[d] : k_scale[d];
    sx[d] = v * rn * (1.f + sc);
    __syncthreads();

    int j = d & 127;
    float c = g_cos[bt][j], s = g_sin[bt][j];
    float x1 = sx[j], x2 = sx[j + 128];
    float out = (d < 128) ? (x1 * c - x2 * s) : (x2 * c + x1 * s);

    if (u < 8) g_q[bt][u][d] = out;
    else       g_k[bt][u - 8][d] = out;
}

// ---------------- attention tile loader (cp.async) --------------------------
__device__ __forceinline__ void attn_issue(
    float* __restrict__ sK, float* __restrict__ sV,
    int k0, int kvl, int hi, int b, int g,
    const float* __restrict__ kb, const float* __restrict__ vb,
    const int* __restrict__ btab, int tid)
{
    const int key = tid >> 4;
    const int j = tid & 15;
    const int kpos = k0 + key;
    const float* kp;
    const float* vp;
    if (kpos < kvl) {
        int blk = btab[b * NBLK + (kpos >> 4)];
        size_t off = (((size_t)blk * NG + g) * KVBLK + (kpos & 15)) * HD;
        kp = kb + off; vp = vb + off;
    } else if (kpos <= hi) {
        int tf = kpos - kvl;
        kp = &g_k[b * TQ + tf][g][0];
        vp = &g_v[b * TQ + tf][g][0];
    } else {
        kp = &g_k[0][0][0];
        vp = &g_v[0][0][0];
    }
    float* dk = sK + key * HD;
    float* dv = sV + key * HD;
#pragma unroll
    for (int c = 0; c < 4; c++) {
        int f = (j + 16 * c) * 4;
        cp_async16(dk + f, kp + f);
        cp_async16(dv + f, vp + f);
    }
}

// ---------------- flash-decode attention: 2q x 8k, cp.async pipeline -------
__global__ void __launch_bounds__(256, 3)
k_attn(const float* __restrict__ k_blocks,
       const float* __restrict__ v_blocks,
       const int* __restrict__ block_tables,
       const int* __restrict__ kv_lens)
{
    extern __shared__ float sm[];
    float* sK0 = sm;
    float* sV0 = sm + 2 * 16 * HD;

    const int bg = blockIdx.x;
    const int b = bg >> 2, g = bg & 3;
    const int sp = blockIdx.y;
    const int tid = threadIdx.x;
    const int warp = tid >> 5, lane = tid & 31;
    const int qp = warp >> 1;
    const int kh = warp & 1;

    const int kvl = kv_lens[b];
    const int lo = max(0, kvl - (WINDOW - 1));
    const int hi = kvl + 3;
    const int L = hi - lo + 1;
    const int chunk = (L + NSPLIT - 1) / NSPLIT;
    const int kstart = lo + sp * chunk;
    const int kend = min(kstart + chunk, hi + 1);

    float4 q1[2], q2[2];
    int post[2];
#pragma unroll
    for (int j = 0; j < 2; j++) {
        int qi = qp * 2 + j;
        int gi = qi >> 2, t = qi & 3;
        q1[j] = *(const float4*)&g_q[b * TQ + t][g * GSZ + gi][lane * 4];
        q2[j] = *(const float4*)&g_q[b * TQ + t][g * GSZ + gi][128 + lane * 4];
        post[j] = kvl + t;
    }

    float m[2] = {-INFINITY, -INFINITY};
    float l[2] = {0.f, 0.f};
    float4 a1[2] = {}, a2[2] = {};

    if (kstart < kend) {
        attn_issue(sK0, sV0, kstart, kvl, hi, b, g,
                   k_blocks, v_blocks, block_tables, tid);
        cp_commit();
    }

    int buf = 0;
    for (int k0 = kstart; k0 < kend; k0 += 16) {
        const int nk = min(16, kend - k0);
        if (k0 + 16 < kend) {
            attn_issue(sK0 + (buf ^ 1) * 16 * HD, sV0 + (buf ^ 1) * 16 * HD,
                       k0 + 16, kvl, hi, b, g,
                       k_blocks, v_blocks, block_tables, tid);
            cp_commit();
            cp_wait<1>();
        } else {
            cp_wait<0>();
        }
        __syncthreads();

        const float* K = sK0 + buf * 16 * HD;
        const float* V = sV0 + buf * 16 * HD;

        float s[2][8];
#pragma unroll
        for (int kk = 0; kk < 8; kk++) {
            const float* kr = K + (kh * 8 + kk) * HD;
            float4 kv1 = *(const float4*)(kr + lane * 4);
            float4 kv2 = *(const float4*)(kr + 128 + lane * 4);
#pragma unroll
            for (int j = 0; j < 2; j++) {
                s[j][kk] = q1[j].x * kv1.x + q1[j].y * kv1.y
                         + q1[j].z * kv1.z + q1[j].w * kv1.w
                         + q2[j].x * kv2.x + q2[j].y * kv2.y
                         + q2[j].z * kv2.z + q2[j].w * kv2.w;
            }
        }
#pragma unroll
        for (int j = 0; j < 2; j++)
#pragma unroll
            for (int kk = 0; kk < 8; kk++) {
                float d = s[j][kk];
#pragma unroll
                for (int o = 16; o; o >>= 1) d += __shfl_xor_sync(0xffffffffu, d, o);
                int kpos = k0 + kh * 8 + kk;
                bool ok = (kh * 8 + kk) < nk && kpos <= post[j]
                          && kpos > post[j] - WINDOW;
                s[j][kk] = ok ? d * 0.0625f : -INFINITY;
            }

#pragma unroll
        for (int j = 0; j < 2; j++) {
            float tm = s[j][0];
#pragma unroll
            for (int kk = 1; kk < 8; kk++) tm = fmaxf(tm, s[j][kk]);
            if (tm == -INFINITY) {
#pragma unroll
                for (int kk = 0; kk < 8; kk++) s[j][kk] = 0.f;
                continue;
            }
            float mn = fmaxf(m[j], tm);
            float co = __expf(m[j] - mn);
            float ls = 0.f;
#pragma unroll
            for (int kk = 0; kk < 8; kk++) {
                s[j][kk] = __expf(s[j][kk] - mn);
                ls += s[j][kk];
            }
            l[j] = l[j] * co + ls;
            a1[j].x *= co; a1[j].y *= co; a1[j].z *= co; a1[j].w *= co;
            a2[j].x *= co; a2[j].y *= co; a2[j].z *= co; a2[j].w *= co;
            m[j] = mn;
        }

#pragma unroll
        for (int kk = 0; kk < 8; kk++) {
            const float* vr = V + (kh * 8 + kk) * HD;
            float4 v1 = *(const float4*)(vr + lane * 4);
            float4 v2 = *(const float4*)(vr + 128 + lane * 4);
#pragma unroll
            for (int j = 0; j < 2; j++) {
                float p = s[j][kk];
                a1[j].x += p * v1.x; a1[j].y += p * v1.y;
                a1[j].z += p * v1.z; a1[j].w += p * v1.w;
                a2[j].x += p * v2.x; a2[j].y += p * v2.y;
                a2[j].z += p * v2.z; a2[j].w += p * v2.w;
            }
        }
        buf ^= 1;
        __syncthreads();
    }

#pragma unroll
    for (int j = 0; j < 2; j++) {
        int qidx = bg * 8 + qp * 2 + j;
        int pi = (qidx * NSPLIT + sp) * 2 + kh;
        if (lane == 0) { g_pm[pi] = m[j]; g_pl[pi] = l[j]; }
        *(float4*)&g_pacc[pi][lane * 4] = a1[j];
        *(float4*)&g_pacc[pi][128 + lane * 4] = a2[j];
    }
}

// ---------------- combine partial softmax -> transposed, tf32-rounded ------
__global__ void k_combine()
{
    const int qidx = blockIdx.x;   // 512
    const int d = threadIdx.x;

    float M = -INFINITY;
#pragma unroll
    for (int s = 0; s < NPART; s++) M = fmaxf(M, g_pm[qidx * NPART + s]);
    float Lt = 0.f, od = 0.f;
#pragma unroll 6
    for (int s = 0; s < NPART; s++) {
        float ms = g_pm[qidx * NPART + s];
        float w = (ms == -INFINITY) ? 0.f : __expf(ms - M);
        Lt += g_pl[qidx * NPART + s] * w;
        od += g_pacc[qidx * NPART + s][d] * w;
    }
    float o = od / Lt;

    int t = qidx & 3;
    int gi = (qidx >> 2) & 1;
    int g = (qidx >> 3) & 3;
    int b = qidx >> 5;
    int f = (g * GSZ + gi) * HD + d;
    g_oT[f][b * TQ + t] = __uint_as_float(f2tf32(o));
}

// ---------------- final split-K reduce to output ---------------------------
__global__ void k_reduce_out(float* __restrict__ out)
{
    int idx = blockIdx.x * blockDim.x + threadIdx.x;   // 64*2048/4
    if (idx >= NTOK * DMODEL / 4) return;
    int bt = idx / (DMODEL / 4), dc = (idx % (DMODEL / 4)) * 4;
    float4 v = {0.f, 0.f, 0.f, 0.f};
#pragma unroll
    for (int s = 0; s < O_SPL; s++) {
        float4 p = *(const float4*)&g_part_out[s][bt][dc];
        v.x += p.x; v.y += p.y; v.z += p.z; v.w += p.w;
    }
    *(float4*)&out[(size_t)bt * DMODEL + dc] = v;
}

// ---------------------------------------------------------------------------
extern "C" void kernel_launch(void* const* d_in, const int* in_sizes, int n_in,
                              void* d_out, int out_size)
{
    const float* x   = (const float*)d_in[0];
    const float* Wq  = (const float*)d_in[1];
    const float* Wk  = (const float*)d_in[2];
    const float* Wv  = (const float*)d_in[3];
    const float* Wo  = (const float*)d_in[4];
    const float* qns = (const float*)d_in[5];
    const float* kns = (const float*)d_in[6];
    const float* kb  = (const float*)d_in[7];
    const float* vb  = (const float*)d_in[8];
    const int* btab  = (const int*)d_in[9];
    const int* kvl   = (const int*)d_in[10];
    float* out = (float*)d_out;

    const int attn_smem = 2 * 16 * HD * 2 * sizeof(float);   // 64 KB
    cudaFuncSetAttribute(k_attn, cudaFuncAttributeMaxDynamicSharedMemorySize,
                         attn_smem);

    k_transpose_x<<<dim3(DMODEL / 32, NTOK / 32), dim3(32, 8)>>>(x);
    k_gemm_qkv<<<dim3(NFQKV / 128, QKV_SPL), 256>>>(Wq, Wk, Wv);
    k_rope_table<<<(NTOK * 128 + 255) / 256, 256>>>(kvl);
    k_normrope<<<dim3(NTOK, 16), 256>>>(qns, kns);
    k_attn<<<dim3(BATCH * NG, NSPLIT), 256, attn_smem>>>(kb, vb, btab, kvl);
    k_combine<<<BATCH * NG * 8, 256>>>();
    k_gemm_o<<<dim3(DMODEL / 128, O_SPL), 256>>>(Wo);
    k_reduce_out<<<(NTOK * DMODEL / 4 + 255) / 256, 256>>>(out);
}

// round 7
// speedup vs baseline: 1.0452x; 1.0452x over previous
#include <cuda_runtime.h>
#include <math.h>

#define BATCH 16
#define TQ 4
#define DMODEL 2048
#define NH 8
#define NG 4
#define GSZ 2
#define HD 256
#define KVBLK 16
#define WINDOW 1024
#define NBLK 257
#define NTOK 64          // BATCH*TQ
#define NFQKV 4096       // 2048 q + 1024 k + 1024 v
#define NSPLIT 8         // attention KV splits
#define NPART (NSPLIT*2) // partials per query (splits x key-halves)
#define NKSPL 8          // GEMM split-K

typedef unsigned long long u64;

// ---------------- scratch (device globals; no allocation allowed) ----------
__device__ float g_part_qkv[NKSPL][NTOK][NFQKV];        // 8 MB
__device__ float g_xT[DMODEL][NTOK];                    // tf32-rounded x^T
__device__ float g_oT[DMODEL][NTOK];                    // tf32-rounded attn-out^T
__device__ float g_q[NTOK][NH][HD];
__device__ float g_k[NTOK][NG][HD];
__device__ float g_v[NTOK][NG][HD];
__device__ float g_cos[NTOK][HD / 2];
__device__ float g_sin[NTOK][HD / 2];
__device__ float g_pacc[BATCH * NG * 8 * NPART][HD];    // 8 MB
__device__ float g_pm[BATCH * NG * 8 * NPART];
__device__ float g_pl[BATCH * NG * 8 * NPART];
__device__ float g_part_out[NKSPL][NTOK][DMODEL];       // 4 MB

// ---------------- cp.async / mma / f32x2 helpers ----------------------------
__device__ __forceinline__ void cp_async16(void* dst, const void* src)
{
    unsigned d = (unsigned)__cvta_generic_to_shared(dst);
    asm volatile("cp.async.cg.shared.global [%0], [%1], 16;\n" :: "r"(d), "l"(src));
}
__device__ __forceinline__ void cp_commit()
{
    asm volatile("cp.async.commit_group;\n");
}
template <int N>
__device__ __forceinline__ void cp_wait()
{
    asm volatile("cp.async.wait_group %0;\n" :: "n"(N));
}
__device__ __forceinline__ unsigned f2tf32(float f)
{
    unsigned u;
    asm("cvt.rna.tf32.f32 %0, %1;" : "=r"(u) : "f"(f));
    return u;
}
__device__ __forceinline__ void mma_tf32(float* d, const unsigned* a, const unsigned* b)
{
    asm volatile(
        "mma.sync.aligned.m16n8k8.row.col.f32.tf32.tf32.f32 "
        "{%0,%1,%2,%3}, {%4,%5,%6,%7}, {%8,%9}, {%0,%1,%2,%3};\n"
        : "+f"(d[0]), "+f"(d[1]), "+f"(d[2]), "+f"(d[3])
        : "r"(a[0]), "r"(a[1]), "r"(a[2]), "r"(a[3]), "r"(b[0]), "r"(b[1]));
}
__device__ __forceinline__ void fma2(u64& acc, u64 a, u64 b)
{
    asm("fma.rn.f32x2 %0, %1, %2, %0;" : "+l"(acc) : "l"(a), "l"(b));
}
__device__ __forceinline__ u64 mul2(u64 a, u64 b)
{
    u64 r;
    asm("mul.rn.f32x2 %0, %1, %2;" : "=l"(r) : "l"(a), "l"(b));
    return r;
}
__device__ __forceinline__ u64 pack2(float lo, float hi)
{
    u64 r;
    asm("mov.b64 %0, {%1, %2};" : "=l"(r) : "f"(lo), "f"(hi));
    return r;
}
__device__ __forceinline__ float sum2(u64 v)
{
    float lo, hi;
    asm("mov.b64 {%0, %1}, %2;" : "=f"(lo), "=f"(hi) : "l"(v));
    return lo + hi;
}

// ---------------- prep: x transpose/round + RoPE table (fused) --------------
__global__ void k_prep(const float* __restrict__ x, const int* __restrict__ kv_lens)
{
    const int blk = blockIdx.x;
    const int tx = threadIdx.x, ty = threadIdx.y;   // (32, 8)
    if (blk < 128) {
        __shared__ float tile[32][33];
        const int kb = (blk & 63) * 32;
        const int tb = (blk >> 6) * 32;
#pragma unroll
        for (int i = 0; i < 32; i += 8)
            tile[ty + i][tx] = x[(size_t)(tb + ty + i) * DMODEL + kb + tx];
        __syncthreads();
#pragma unroll
        for (int i = 0; i < 32; i += 8) {
            float v = tile[tx][ty + i];
            g_xT[kb + ty + i][tb + tx] = __uint_as_float(f2tf32(v));
        }
    } else {
        int idx = (blk - 128) * 256 + ty * 32 + tx;   // 32 blocks cover 64*128
        int bt = idx >> 7, j = idx & 127;
        int b = bt >> 2, t = bt & 3;
        int pos = kv_lens[b] + t;
        double inv = exp(-((double)j / 128.0) * log(10000.0));
        double ang = (double)pos * inv;
        double sd, cd;
        sincos(ang, &sd, &cd);
        g_cos[bt][j] = (float)cd;
        g_sin[bt][j] = (float)sd;
    }
}

// ---------------- tf32 tensor-core split-K GEMM (R5 config) -----------------
// CTA: 64 tokens x 64 features, Kc = 256 (8 chunks of 32, double-buffered).
template <int NF>
__device__ __forceinline__ void gemm_tc(
    const float* __restrict__ AT,
    const float* __restrict__ W0, int n0,
    const float* __restrict__ W1, int n1,
    const float* __restrict__ W2,
    float* __restrict__ part)
{
    __shared__ float As[2][32][72];
    __shared__ float Ws[2][64][36];

    const int fbase = blockIdx.x * 64;
    const int split = blockIdx.y;
    const int tid = threadIdx.x;
    const int lane = tid & 31, warp = tid >> 5;
    const int wm = warp >> 2, wn = warp & 3;
    const int kbase = split * 256;
    const int gid = lane >> 2, tig = lane & 3;

    float acc[2][2][4] = {};

    auto issue = [&](int c, int buf) {
        const int kg = kbase + c * 32;
#pragma unroll
        for (int r = 0; r < 2; r++) {
            int o = tid * 2 + r;
            int row = o >> 4, seg = o & 15;
            cp_async16(&As[buf][row][seg * 4],
                       &AT[(size_t)(kg + row) * NTOK + seg * 4]);
        }
#pragma unroll
        for (int r = 0; r < 2; r++) {
            int o = tid * 2 + r;
            int n = o >> 3, seg = o & 7;
            int f = fbase + n;
            const float* wr;
            if (f < n0)            wr = W0 + (size_t)f * DMODEL;
            else if (f < n0 + n1)  wr = W1 + (size_t)(f - n0) * DMODEL;
            else                   wr = W2 + (size_t)(f - n0 - n1) * DMODEL;
            cp_async16(&Ws[buf][n][seg * 4], wr + kg + seg * 4);
        }
        cp_commit();
    };

    issue(0, 0);
    int buf = 0;
    for (int c = 0; c < 8; c++) {
        if (c < 7) { issue(c + 1, buf ^ 1); cp_wait<1>(); }
        else       cp_wait<0>();
        __syncthreads();
#pragma unroll
        for (int ks = 0; ks < 4; ks++) {
            const int k = ks * 8 + tig;
            unsigned aF[2][4], bF[2][2];
#pragma unroll
            for (int mt = 0; mt < 2; mt++) {
                int m = wm * 32 + mt * 16 + gid;
                aF[mt][0] = __float_as_uint(As[buf][k][m]);
                aF[mt][1] = __float_as_uint(As[buf][k][m + 8]);
                aF[mt][2] = __float_as_uint(As[buf][k + 4][m]);
                aF[mt][3] = __float_as_uint(As[buf][k + 4][m + 8]);
            }
#pragma unroll
            for (int nt = 0; nt < 2; nt++) {
                int n = wn * 16 + nt * 8 + gid;
                bF[nt][0] = f2tf32(Ws[buf][n][k]);
                bF[nt][1] = f2tf32(Ws[buf][n][k + 4]);
            }
#pragma unroll
            for (int mt = 0; mt < 2; mt++)
#pragma unroll
                for (int nt = 0; nt < 2; nt++)
                    mma_tf32(acc[mt][nt], aF[mt], bF[nt]);
        }
        buf ^= 1;
        __syncthreads();
    }

#pragma unroll
    for (int mt = 0; mt < 2; mt++)
#pragma unroll
        for (int nt = 0; nt < 2; nt++) {
            int m = wm * 32 + mt * 16 + gid;
            int f = fbase + wn * 16 + nt * 8 + tig * 2;
            *(float2*)&part[((size_t)split * NTOK + m) * NF + f] =
                make_float2(acc[mt][nt][0], acc[mt][nt][1]);
            *(float2*)&part[((size_t)split * NTOK + m + 8) * NF + f] =
                make_float2(acc[mt][nt][2], acc[mt][nt][3]);
        }
}

__global__ void __launch_bounds__(256)
k_gemm_qkv(const float* __restrict__ Wq,
           const float* __restrict__ Wk,
           const float* __restrict__ Wv)
{
    gemm_tc<NFQKV>(&g_xT[0][0], Wq, 2048, Wk, 1024, Wv, &g_part_qkv[0][0][0]);
}

__global__ void __launch_bounds__(256)
k_gemm_o(const float* __restrict__ Wo)
{
    gemm_tc<DMODEL>(&g_oT[0][0], Wo, 2048, Wo, 0, Wo, &g_part_out[0][0][0]);
}

// ---------------- split-K reduce + RMSNorm + RoPE + store q/k/v ------------
__global__ void k_normrope(const float* __restrict__ q_scale,
                           const float* __restrict__ k_scale)
{
    const int bt = blockIdx.x;
    const int u = blockIdx.y;
    const int d = threadIdx.x;      // 0..255

    int f;
    if (u < 8)       f = u * HD + d;
    else if (u < 12) f = 2048 + (u - 8) * HD + d;
    else             f = 3072 + (u - 12) * HD + d;

    float v = 0.f;
#pragma unroll
    for (int s = 0; s < NKSPL; s++) v += g_part_qkv[s][bt][f];

    if (u >= 12) { g_v[bt][u - 12][d] = v; return; }

    __shared__ float red[256];
    __shared__ float sx[256];
    red[d] = v * v;
    __syncthreads();
    for (int s = 128; s > 0; s >>= 1) {
        if (d < s) red[d] += red[d + s];
        __syncthreads();
    }
    float rn = rsqrtf(red[0] / (float)HD + 1e-6f);
    float sc = (u < 8) ? q_scale[d] : k_scale[d];
    sx[d] = v * rn * (1.f + sc);
    __syncthreads();

    int j = d & 127;
    float c = g_cos[bt][j], s = g_sin[bt][j];
    float x1 = sx[j], x2 = sx[j + 128];
    float out = (d < 128) ? (x1 * c - x2 * s) : (x2 * c + x1 * s);

    if (u < 8) g_q[bt][u][d] = out;
    else       g_k[bt][u - 8][d] = out;
}

// ---------------- attention tile loader (cp.async) --------------------------
__device__ __forceinline__ void attn_issue(
    float* __restrict__ sK, float* __restrict__ sV,
    int k0, int kvl, int hi, int b, int g,
    const float* __restrict__ kb, const float* __restrict__ vb,
    const int* __restrict__ btab, int tid)
{
    const int key = tid >> 4;
    const int j = tid & 15;
    const int kpos = k0 + key;
    const float* kp;
    const float* vp;
    if (kpos < kvl) {
        int blk = btab[b * NBLK + (kpos >> 4)];
        size_t off = (((size_t)blk * NG + g) * KVBLK + (kpos & 15)) * HD;
        kp = kb + off; vp = vb + off;
    } else if (kpos <= hi) {
        int tf = kpos - kvl;
        kp = &g_k[b * TQ + tf][g][0];
        vp = &g_v[b * TQ + tf][g][0];
    } else {
        kp = &g_k[0][0][0];
        vp = &g_v[0][0][0];
    }
    float* dk = sK + key * HD;
    float* dv = sV + key * HD;
#pragma unroll
    for (int c = 0; c < 4; c++) {
        int f = (j + 16 * c) * 4;
        cp_async16(dk + f, kp + f);
        cp_async16(dv + f, vp + f);
    }
}

// ---------------- flash-decode attention: 2q x 8k, f32x2 math ---------------
__global__ void __launch_bounds__(256, 3)
k_attn(const float* __restrict__ k_blocks,
       const float* __restrict__ v_blocks,
       const int* __restrict__ block_tables,
       const int* __restrict__ kv_lens)
{
    extern __shared__ float sm[];
    float* sK0 = sm;
    float* sV0 = sm + 2 * 16 * HD;

    const int bg = blockIdx.x;
    const int b = bg >> 2, g = bg & 3;
    const int sp = blockIdx.y;
    const int tid = threadIdx.x;
    const int warp = tid >> 5, lane = tid & 31;
    const int qp = warp >> 1;
    const int kh = warp & 1;

    const int kvl = kv_lens[b];
    const int lo = max(0, kvl - (WINDOW - 1));
    const int hi = kvl + 3;
    const int L = hi - lo + 1;
    const int chunk = (L + NSPLIT - 1) / NSPLIT;
    const int kstart = lo + sp * chunk;
    const int kend = min(kstart + chunk, hi + 1);

    // queries packed as 4 x f32x2 per half (8 dims per lane)
    u64 qv[2][4];
    int post[2];
#pragma unroll
    for (int j = 0; j < 2; j++) {
        int qi = qp * 2 + j;
        int gi = qi >> 2, t = qi & 3;
        ulonglong2 a = *(const ulonglong2*)&g_q[b * TQ + t][g * GSZ + gi][lane * 4];
        ulonglong2 c = *(const ulonglong2*)&g_q[b * TQ + t][g * GSZ + gi][128 + lane * 4];
        qv[j][0] = a.x; qv[j][1] = a.y; qv[j][2] = c.x; qv[j][3] = c.y;
        post[j] = kvl + t;
    }

    float m[2] = {-INFINITY, -INFINITY};
    float l[2] = {0.f, 0.f};
    u64 av[2][4] = {};          // packed accumulators (8 dims per lane)

    if (kstart < kend) {
        attn_issue(sK0, sV0, kstart, kvl, hi, b, g,
                   k_blocks, v_blocks, block_tables, tid);
        cp_commit();
    }

    int buf = 0;
    for (int k0 = kstart; k0 < kend; k0 += 16) {
        const int nk = min(16, kend - k0);
        if (k0 + 16 < kend) {
            attn_issue(sK0 + (buf ^ 1) * 16 * HD, sV0 + (buf ^ 1) * 16 * HD,
                       k0 + 16, kvl, hi, b, g,
                       k_blocks, v_blocks, block_tables, tid);
            cp_commit();
            cp_wait<1>();
        } else {
            cp_wait<0>();
        }
        __syncthreads();

        const float* K = sK0 + buf * 16 * HD;
        const float* V = sV0 + buf * 16 * HD;

        // ---- scores: packed f32x2 dot products ----
        float s[2][8];
#pragma unroll
        for (int kk = 0; kk < 8; kk++) {
            const float* kr = K + (kh * 8 + kk) * HD;
            ulonglong2 kA = *(const ulonglong2*)(kr + lane * 4);
            ulonglong2 kB = *(const ulonglong2*)(kr + 128 + lane * 4);
#pragma unroll
            for (int j = 0; j < 2; j++) {
                u64 d2 = 0;                 // bits of (0.f, 0.f)
                fma2(d2, qv[j][0], kA.x);
                fma2(d2, qv[j][1], kA.y);
                fma2(d2, qv[j][2], kB.x);
                fma2(d2, qv[j][3], kB.y);
                s[j][kk] = sum2(d2);
            }
        }
#pragma unroll
        for (int j = 0; j < 2; j++)
#pragma unroll
            for (int kk = 0; kk < 8; kk++) {
                float d = s[j][kk];
#pragma unroll
                for (int o = 16; o; o >>= 1) d += __shfl_xor_sync(0xffffffffu, d, o);
                int kpos = k0 + kh * 8 + kk;
                bool ok = (kh * 8 + kk) < nk && kpos <= post[j]
                          && kpos > post[j] - WINDOW;
                s[j][kk] = ok ? d * 0.0625f : -INFINITY;
            }

        // ---- online softmax update ----
#pragma unroll
        for (int j = 0; j < 2; j++) {
            float tm = s[j][0];
#pragma unroll
            for (int kk = 1; kk < 8; kk++) tm = fmaxf(tm, s[j][kk]);
            if (tm == -INFINITY) {
#pragma unroll
                for (int kk = 0; kk < 8; kk++) s[j][kk] = 0.f;
                continue;
            }
            float mn = fmaxf(m[j], tm);
            float co = __expf(m[j] - mn);
            float ls = 0.f;
#pragma unroll
            for (int kk = 0; kk < 8; kk++) {
                s[j][kk] = __expf(s[j][kk] - mn);
                ls += s[j][kk];
            }
            l[j] = l[j] * co + ls;
            u64 cop = pack2(co, co);
#pragma unroll
            for (int i = 0; i < 4; i++) av[j][i] = mul2(av[j][i], cop);
            m[j] = mn;
        }

        // ---- PV: packed f32x2 accumulate ----
#pragma unroll
        for (int kk = 0; kk < 8; kk++) {
            const float* vr = V + (kh * 8 + kk) * HD;
            ulonglong2 vA = *(const ulonglong2*)(vr + lane * 4);
            ulonglong2 vB = *(const ulonglong2*)(vr + 128 + lane * 4);
#pragma unroll
            for (int j = 0; j < 2; j++) {
                u64 pp = pack2(s[j][kk], s[j][kk]);
                fma2(av[j][0], pp, vA.x);
                fma2(av[j][1], pp, vA.y);
                fma2(av[j][2], pp, vB.x);
                fma2(av[j][3], pp, vB.y);
            }
        }
        buf ^= 1;
        __syncthreads();
    }

#pragma unroll
    for (int j = 0; j < 2; j++) {
        int qidx = bg * 8 + qp * 2 + j;
        int pi = (qidx * NSPLIT + sp) * 2 + kh;
        if (lane == 0) { g_pm[pi] = m[j]; g_pl[pi] = l[j]; }
        ulonglong2 oA = {av[j][0], av[j][1]};
        ulonglong2 oB = {av[j][2], av[j][3]};
        *(ulonglong2*)&g_pacc[pi][lane * 4] = oA;
        *(ulonglong2*)&g_pacc[pi][128 + lane * 4] = oB;
    }
}

// ---------------- combine partial softmax -> transposed, tf32-rounded ------
__global__ void k_combine()
{
    const int qidx = blockIdx.x;   // 512
    const int d = threadIdx.x;

    float M = -INFINITY;
#pragma unroll
    for (int s = 0; s < NPART; s++) M = fmaxf(M, g_pm[qidx * NPART + s]);
    float Lt = 0.f, od = 0.f;
#pragma unroll 8
    for (int s = 0; s < NPART; s++) {
        float ms = g_pm[qidx * NPART + s];
        float w = (ms == -INFINITY) ? 0.f : __expf(ms - M);
        Lt += g_pl[qidx * NPART + s] * w;
        od += g_pacc[qidx * NPART + s][d] * w;
    }
    float o = od / Lt;

    int t = qidx & 3;
    int gi = (qidx >> 2) & 1;
    int g = (qidx >> 3) & 3;
    int b = qidx >> 5;
    int f = (g * GSZ + gi) * HD + d;
    g_oT[f][b * TQ + t] = __uint_as_float(f2tf32(o));
}

// ---------------- final split-K reduce to output ---------------------------
__global__ void k_reduce_out(float* __restrict__ out)
{
    int idx = blockIdx.x * blockDim.x + threadIdx.x;   // 64*2048/4
    if (idx >= NTOK * DMODEL / 4) return;
    int bt = idx / (DMODEL / 4), dc = (idx % (DMODEL / 4)) * 4;
    float4 v = {0.f, 0.f, 0.f, 0.f};
#pragma unroll
    for (int s = 0; s < NKSPL; s++) {
        float4 p = *(const float4*)&g_part_out[s][bt][dc];
        v.x += p.x; v.y += p.y; v.z += p.z; v.w += p.w;
    }
    *(float4*)&out[(size_t)bt * DMODEL + dc] = v;
}

// ---------------------------------------------------------------------------
extern "C" void kernel_launch(void* const* d_in, const int* in_sizes, int n_in,
                              void* d_out, int out_size)
{
    const float* x   = (const float*)d_in[0];
    const float* Wq  = (const float*)d_in[1];
    const float* Wk  = (const float*)d_in[2];
    const float* Wv  = (const float*)d_in[3];
    const float* Wo  = (const float*)d_in[4];
    const float* qns = (const float*)d_in[5];
    const float* kns = (const float*)d_in[6];
    const float* kb  = (const float*)d_in[7];
    const float* vb  = (const float*)d_in[8];
    const int* btab  = (const int*)d_in[9];
    const int* kvl   = (const int*)d_in[10];
    float* out = (float*)d_out;

    const int attn_smem = 2 * 16 * HD * 2 * sizeof(float);   // 64 KB
    cudaFuncSetAttribute(k_attn, cudaFuncAttributeMaxDynamicSharedMemorySize,
                         attn_smem);

    k_prep<<<160, dim3(32, 8)>>>(x, kvl);
    k_gemm_qkv<<<dim3(NFQKV / 64, NKSPL), 256>>>(Wq, Wk, Wv);
    k_normrope<<<dim3(NTOK, 16), 256>>>(qns, kns);
    k_attn<<<dim3(BATCH * NG, NSPLIT), 256, attn_smem>>>(kb, vb, btab, kvl);
    k_combine<<<BATCH * NG * 8, 256>>>();
    k_gemm_o<<<dim3(DMODEL / 64, NKSPL), 256>>>(Wo);
    k_reduce_out<<<(NTOK * DMODEL / 4 + 255) / 256, 256>>>(out);
}